// round 1
// baseline (speedup 1.0000x reference)
#include <cuda_runtime.h>
#include <cuda_bf16.h>
#include <math.h>

// Problem constants (fixed shapes from reference)
#define B_  4
#define T_  2048
#define C_  1024
#define H_  16
#define HD_ 64
#define M_ROWS (B_ * T_)          // 8192
#define QKV_N  (3 * C_)           // 3072

// -------- scratch (device globals; no allocation allowed) --------
__device__ float g_qkv[(size_t)M_ROWS * QKV_N];        // 96 MB (B*T, 3C)
__device__ float g_q[(size_t)B_ * H_ * T_ * HD_];      // 32 MB (B*H, T, hd) roped+scaled
__device__ float g_k[(size_t)B_ * H_ * T_ * HD_];      // 32 MB
__device__ float g_v[(size_t)B_ * H_ * T_ * HD_];      // 32 MB
__device__ float g_y[(size_t)M_ROWS * C_];             // 32 MB (B, T, C) attention output

// ============================================================================
// GEMM (NT): C[m,n] = sum_k A[m*K+k] * B[n*K+k]
// 128x128 tile, BK=16, 256 threads, 8x8 per-thread microtile.
// ============================================================================
#define BM 128
#define BN 128
#define BK 16

__global__ __launch_bounds__(256) void gemm_nt(
    const float* __restrict__ A, const float* __restrict__ Bm,
    float* __restrict__ C, int M, int N, int K)
{
    __shared__ float As[BK][BM];
    __shared__ float Bs[BK][BN];

    const int bm = blockIdx.y * BM;
    const int bn = blockIdx.x * BN;
    const int tid = threadIdx.x;
    const int tx = tid & 15;       // 0..15
    const int ty = tid >> 4;       // 0..15

    const int lrow = tid >> 2;         // 0..63
    const int lcol = (tid & 3) * 4;    // 0,4,8,12

    float acc[8][8];
#pragma unroll
    for (int i = 0; i < 8; ++i)
#pragma unroll
        for (int j = 0; j < 8; ++j) acc[i][j] = 0.0f;

    for (int k0 = 0; k0 < K; k0 += BK) {
        // load A tile (128 x 16), store transposed As[k][m]
#pragma unroll
        for (int p = 0; p < 2; ++p) {
            int r = lrow + p * 64;
            float4 v = *(const float4*)(A + (size_t)(bm + r) * K + k0 + lcol);
            As[lcol + 0][r] = v.x;
            As[lcol + 1][r] = v.y;
            As[lcol + 2][r] = v.z;
            As[lcol + 3][r] = v.w;
        }
        // load B tile (128 x 16), store transposed Bs[k][n]
#pragma unroll
        for (int p = 0; p < 2; ++p) {
            int r = lrow + p * 64;
            float4 v = *(const float4*)(Bm + (size_t)(bn + r) * K + k0 + lcol);
            Bs[lcol + 0][r] = v.x;
            Bs[lcol + 1][r] = v.y;
            Bs[lcol + 2][r] = v.z;
            Bs[lcol + 3][r] = v.w;
        }
        __syncthreads();

#pragma unroll
        for (int kk = 0; kk < BK; ++kk) {
            float4 a0 = *(const float4*)&As[kk][ty * 8];
            float4 a1 = *(const float4*)&As[kk][ty * 8 + 4];
            float4 b0 = *(const float4*)&Bs[kk][tx * 8];
            float4 b1 = *(const float4*)&Bs[kk][tx * 8 + 4];
            float ra[8] = {a0.x, a0.y, a0.z, a0.w, a1.x, a1.y, a1.z, a1.w};
            float rb[8] = {b0.x, b0.y, b0.z, b0.w, b1.x, b1.y, b1.z, b1.w};
#pragma unroll
            for (int i = 0; i < 8; ++i)
#pragma unroll
                for (int j = 0; j < 8; ++j)
                    acc[i][j] = fmaf(ra[i], rb[j], acc[i][j]);
        }
        __syncthreads();
    }

#pragma unroll
    for (int i = 0; i < 8; ++i) {
        float4* cp = (float4*)(C + (size_t)(bm + ty * 8 + i) * N + bn + tx * 8);
        cp[0] = make_float4(acc[i][0], acc[i][1], acc[i][2], acc[i][3]);
        cp[1] = make_float4(acc[i][4], acc[i][5], acc[i][6], acc[i][7]);
    }
}

// ============================================================================
// RoPE + rearrange: qkv (B*T, 3C) -> Q/K/V (B*H, T, hd)
// Q gets the 1/sqrt(hd) scale folded in. One thread per (b,t,h,pair).
// ============================================================================
__global__ __launch_bounds__(256) void rope_rearrange(const float* __restrict__ qkv)
{
    int idx = blockIdx.x * blockDim.x + threadIdx.x;
    if (idx >= B_ * T_ * H_ * (HD_ / 2)) return;

    int i = idx & 31;               // pair index 0..31
    int h = (idx >> 5) & 15;
    int t = (idx >> 9) & 2047;
    int b = idx >> 20;

    const float* src = qkv + (size_t)(b * T_ + t) * QKV_N + h * HD_ + 2 * i;

    // angle in double to keep rope rounding negligible vs 1e-3 budget
    double inv = exp2(-(double)i * (13.287712379549449595 / 32.0)); // 10000^(-i/32)
    double ang = (double)t * inv;
    double ds, dc;
    sincos(ang, &ds, &dc);
    float s = (float)ds, c = (float)dc;

    float q0 = src[0],       q1 = src[1];
    float k0 = src[C_],      k1 = src[C_ + 1];
    float2 v2 = *(const float2*)(src + 2 * C_);

    size_t dst = ((size_t)(b * H_ + h) * T_ + t) * HD_ + 2 * i;
    const float qs = 0.125f;  // 1/sqrt(64)
    g_q[dst]     = (q0 * c - q1 * s) * qs;
    g_q[dst + 1] = (q0 * s + q1 * c) * qs;
    g_k[dst]     = k0 * c - k1 * s;
    g_k[dst + 1] = k0 * s + k1 * c;
    *(float2*)(g_v + dst) = v2;
}

// ============================================================================
// Flash attention: per (b,h), 64-query tiles over 64-key tiles, hd=64.
// 256 threads (16x16), each owns a 4x4 microtile. Online softmax.
// smem: Qs,Ks [d][r] transposed; Vs [k][d]; Ps [r][k]. 4 * 16KB = 64KB dynamic.
// Output written directly in (B, T, C) layout into g_y.
// ============================================================================
__global__ __launch_bounds__(256) void flash_attn()
{
    extern __shared__ float smem[];
    float* Qs = smem;              // [d][r]  64*64
    float* Ks = smem + 4096;       // [d][c]
    float* Vs = smem + 8192;       // [k][d]
    float* Ps = smem + 12288;      // [r][k]

    const int bh = blockIdx.y;                // 0..63
    const int b  = bh >> 4;
    const int h  = bh & 15;
    const int q0 = blockIdx.x * 64;

    const float* Qb = g_q + (size_t)bh * T_ * HD_;
    const float* Kb = g_k + (size_t)bh * T_ * HD_;
    const float* Vb = g_v + (size_t)bh * T_ * HD_;

    const int tid = threadIdx.x;
    const int tx = tid & 15;
    const int ty = tid >> 4;
    const int r0 = ty * 4;
    const int c0 = tx * 4;

    // loader mapping: each thread loads 4 float4 of one 64x64 tile
    const int lr = tid >> 2;          // row 0..63
    const int lchunk = (tid & 3) * 16; // starting d, 0/16/32/48

    // Load Q tile transposed: Qs[d][r]
#pragma unroll
    for (int p = 0; p < 4; ++p) {
        int d = lchunk + p * 4;
        float4 v = *(const float4*)(Qb + (size_t)(q0 + lr) * HD_ + d);
        Qs[(d + 0) * 64 + lr] = v.x;
        Qs[(d + 1) * 64 + lr] = v.y;
        Qs[(d + 2) * 64 + lr] = v.z;
        Qs[(d + 3) * 64 + lr] = v.w;
    }

    float O[4][4];
    float m[4], l[4];
#pragma unroll
    for (int i = 0; i < 4; ++i) {
        m[i] = -3.0e38f; l[i] = 0.0f;
#pragma unroll
        for (int j = 0; j < 4; ++j) O[i][j] = 0.0f;
    }

    for (int kt = 0; kt < T_ / 64; ++kt) {
        const int k0 = kt * 64;
        __syncthreads();   // protect Ks/Vs/Ps from previous iteration readers
        // Load K transposed Ks[d][c], V natural Vs[k][d]
#pragma unroll
        for (int p = 0; p < 4; ++p) {
            int d = lchunk + p * 4;
            float4 kv = *(const float4*)(Kb + (size_t)(k0 + lr) * HD_ + d);
            Ks[(d + 0) * 64 + lr] = kv.x;
            Ks[(d + 1) * 64 + lr] = kv.y;
            Ks[(d + 2) * 64 + lr] = kv.z;
            Ks[(d + 3) * 64 + lr] = kv.w;
            float4 vv = *(const float4*)(Vb + (size_t)(k0 + lr) * HD_ + d);
            *(float4*)(Vs + lr * 64 + d) = vv;
        }
        __syncthreads();

        // S = Q K^T  (already scaled via Q)
        float acc[4][4];
#pragma unroll
        for (int i = 0; i < 4; ++i)
#pragma unroll
            for (int j = 0; j < 4; ++j) acc[i][j] = 0.0f;

#pragma unroll 8
        for (int d = 0; d < 64; ++d) {
            float4 a4 = *(const float4*)(Qs + d * 64 + r0);
            float4 b4 = *(const float4*)(Ks + d * 64 + c0);
            float ra[4] = {a4.x, a4.y, a4.z, a4.w};
            float rb[4] = {b4.x, b4.y, b4.z, b4.w};
#pragma unroll
            for (int i = 0; i < 4; ++i)
#pragma unroll
                for (int j = 0; j < 4; ++j)
                    acc[i][j] = fmaf(ra[i], rb[j], acc[i][j]);
        }

        // online softmax per row (rows shared by 16 tx-lanes; shfl stays in 16-group)
#pragma unroll
        for (int i = 0; i < 4; ++i) {
            float mt = fmaxf(fmaxf(acc[i][0], acc[i][1]), fmaxf(acc[i][2], acc[i][3]));
#pragma unroll
            for (int off = 1; off < 16; off <<= 1)
                mt = fmaxf(mt, __shfl_xor_sync(0xffffffffu, mt, off));
            float mn = fmaxf(m[i], mt);
            float corr = expf(m[i] - mn);
            m[i] = mn;
            l[i] *= corr;
#pragma unroll
            for (int j = 0; j < 4; ++j) O[i][j] *= corr;

            float rs = 0.0f;
#pragma unroll
            for (int j = 0; j < 4; ++j) {
                float p = expf(acc[i][j] - mn);
                acc[i][j] = p;
                rs += p;
            }
#pragma unroll
            for (int off = 1; off < 16; off <<= 1)
                rs += __shfl_xor_sync(0xffffffffu, rs, off);
            l[i] += rs;
        }

        // write P tile
#pragma unroll
        for (int i = 0; i < 4; ++i)
            *(float4*)(Ps + (r0 + i) * 64 + c0) =
                make_float4(acc[i][0], acc[i][1], acc[i][2], acc[i][3]);
        __syncthreads();

        // O += P @ V
#pragma unroll 8
        for (int kk = 0; kk < 64; ++kk) {
            float4 b4 = *(const float4*)(Vs + kk * 64 + c0);
            float rb[4] = {b4.x, b4.y, b4.z, b4.w};
            float pa[4];
#pragma unroll
            for (int i = 0; i < 4; ++i) pa[i] = Ps[(r0 + i) * 64 + kk];
#pragma unroll
            for (int i = 0; i < 4; ++i)
#pragma unroll
                for (int j = 0; j < 4; ++j)
                    O[i][j] = fmaf(pa[i], rb[j], O[i][j]);
        }
    }

    // epilogue: normalize, write to (B, T, C)
#pragma unroll
    for (int i = 0; i < 4; ++i) {
        float rl = 1.0f / l[i];
        float4 o = make_float4(O[i][0] * rl, O[i][1] * rl, O[i][2] * rl, O[i][3] * rl);
        *(float4*)(g_y + (size_t)(b * T_ + q0 + r0 + i) * C_ + h * HD_ + c0) = o;
    }
}

// ============================================================================
// launch
// ============================================================================
extern "C" void kernel_launch(void* const* d_in, const int* in_sizes, int n_in,
                              void* d_out, int out_size)
{
    const float* x      = (const float*)d_in[0];
    const float* w_attn = (const float*)d_in[1];
    const float* w_proj = (const float*)d_in[2];
    float* out = (float*)d_out;

    float* qkv_ptr; cudaGetSymbolAddress((void**)&qkv_ptr, g_qkv);
    float* y_ptr;   cudaGetSymbolAddress((void**)&y_ptr,   g_y);

    // allow 64KB dynamic smem for flash kernel (idempotent)
    cudaFuncSetAttribute(flash_attn, cudaFuncAttributeMaxDynamicSharedMemorySize, 65536);

    // 1) QKV = x @ w_attn^T : (8192, 3072)
    gemm_nt<<<dim3(QKV_N / BN, M_ROWS / BM), 256>>>(x, w_attn, qkv_ptr, M_ROWS, QKV_N, C_);

    // 2) RoPE + rearrange
    {
        int n = B_ * T_ * H_ * (HD_ / 2);
        rope_rearrange<<<(n + 255) / 256, 256>>>(qkv_ptr);
    }

    // 3) flash attention -> g_y (B,T,C)
    flash_attn<<<dim3(T_ / 64, B_ * H_), 256, 65536>>>();

    // 4) out = y @ w_proj^T : (8192, 1024)
    gemm_nt<<<dim3(C_ / BN, M_ROWS / BM), 256>>>(y_ptr, w_proj, out, M_ROWS, C_, C_);
}

// round 3
// speedup vs baseline: 1.1430x; 1.1430x over previous
#include <cuda_runtime.h>
#include <cuda_bf16.h>
#include <math.h>

// Problem constants (fixed shapes from reference)
#define B_  4
#define T_  2048
#define C_  1024
#define H_  16
#define HD_ 64
#define M_ROWS (B_ * T_)          // 8192
#define QKV_N  (3 * C_)           // 3072

// -------- scratch (device globals; no allocation allowed) --------
__device__ float g_qkv[(size_t)M_ROWS * QKV_N];        // 96 MB (B*T, 3C)
__device__ float g_q[(size_t)B_ * H_ * T_ * HD_];      // 32 MB (B*H, T, hd) roped+scaled
__device__ float g_k[(size_t)B_ * H_ * T_ * HD_];      // 32 MB
__device__ float g_v[(size_t)B_ * H_ * T_ * HD_];      // 32 MB
__device__ float g_y[(size_t)M_ROWS * C_];             // 32 MB (B, T, C) attention output

// ============================================================================
// GEMM (NT): C[m,n] = sum_k A[m*K+k] * B[n*K+k]
// 128x128 tile, BK=16, 256 threads, 8x8 microtile, double-buffered smem with
// register-staged prefetch (one sync per K-slab).
// ============================================================================
#define BM 128
#define BN 128
#define BK 16

__global__ __launch_bounds__(256, 2) void gemm_nt(
    const float* __restrict__ A, const float* __restrict__ Bm,
    float* __restrict__ C, int M, int N, int K)
{
    __shared__ float As[2][BK][BM];
    __shared__ float Bs[2][BK][BN];

    const int bm = blockIdx.y * BM;
    const int bn = blockIdx.x * BN;
    const int tid = threadIdx.x;
    const int tx = tid & 15;       // 0..15
    const int ty = tid >> 4;       // 0..15

    const int lrow = tid >> 2;         // 0..63
    const int lcol = (tid & 3) * 4;    // 0,4,8,12

    const float* Ab = A  + (size_t)(bm + lrow) * K + lcol;
    const float* Bb = Bm + (size_t)(bn + lrow) * K + lcol;
    const size_t rowK64 = (size_t)64 * K;

    float acc[8][8];
#pragma unroll
    for (int i = 0; i < 8; ++i)
#pragma unroll
        for (int j = 0; j < 8; ++j) acc[i][j] = 0.0f;

    // ---- load tile 0 into buffer 0 ----
    {
        float4 a0 = *(const float4*)(Ab);
        float4 a1 = *(const float4*)(Ab + rowK64);
        float4 b0 = *(const float4*)(Bb);
        float4 b1 = *(const float4*)(Bb + rowK64);
        As[0][lcol + 0][lrow] = a0.x; As[0][lcol + 1][lrow] = a0.y;
        As[0][lcol + 2][lrow] = a0.z; As[0][lcol + 3][lrow] = a0.w;
        As[0][lcol + 0][lrow + 64] = a1.x; As[0][lcol + 1][lrow + 64] = a1.y;
        As[0][lcol + 2][lrow + 64] = a1.z; As[0][lcol + 3][lrow + 64] = a1.w;
        Bs[0][lcol + 0][lrow] = b0.x; Bs[0][lcol + 1][lrow] = b0.y;
        Bs[0][lcol + 2][lrow] = b0.z; Bs[0][lcol + 3][lrow] = b0.w;
        Bs[0][lcol + 0][lrow + 64] = b1.x; Bs[0][lcol + 1][lrow + 64] = b1.y;
        Bs[0][lcol + 2][lrow + 64] = b1.z; Bs[0][lcol + 3][lrow + 64] = b1.w;
    }
    __syncthreads();

    int p = 0;
    for (int k0 = BK; k0 < K; k0 += BK) {
        // prefetch next slab into registers
        float4 na0 = *(const float4*)(Ab + k0);
        float4 na1 = *(const float4*)(Ab + k0 + rowK64);
        float4 nb0 = *(const float4*)(Bb + k0);
        float4 nb1 = *(const float4*)(Bb + k0 + rowK64);

        // compute on buffer p
#pragma unroll
        for (int kk = 0; kk < BK; ++kk) {
            float4 a0 = *(const float4*)&As[p][kk][ty * 8];
            float4 a1 = *(const float4*)&As[p][kk][ty * 8 + 4];
            float4 b0 = *(const float4*)&Bs[p][kk][tx * 8];
            float4 b1 = *(const float4*)&Bs[p][kk][tx * 8 + 4];
            float ra[8] = {a0.x, a0.y, a0.z, a0.w, a1.x, a1.y, a1.z, a1.w};
            float rb[8] = {b0.x, b0.y, b0.z, b0.w, b1.x, b1.y, b1.z, b1.w};
#pragma unroll
            for (int i = 0; i < 8; ++i)
#pragma unroll
                for (int j = 0; j < 8; ++j)
                    acc[i][j] = fmaf(ra[i], rb[j], acc[i][j]);
        }

        // stage prefetch into the other buffer
        const int q = p ^ 1;
        As[q][lcol + 0][lrow] = na0.x; As[q][lcol + 1][lrow] = na0.y;
        As[q][lcol + 2][lrow] = na0.z; As[q][lcol + 3][lrow] = na0.w;
        As[q][lcol + 0][lrow + 64] = na1.x; As[q][lcol + 1][lrow + 64] = na1.y;
        As[q][lcol + 2][lrow + 64] = na1.z; As[q][lcol + 3][lrow + 64] = na1.w;
        Bs[q][lcol + 0][lrow] = nb0.x; Bs[q][lcol + 1][lrow] = nb0.y;
        Bs[q][lcol + 2][lrow] = nb0.z; Bs[q][lcol + 3][lrow] = nb0.w;
        Bs[q][lcol + 0][lrow + 64] = nb1.x; Bs[q][lcol + 1][lrow + 64] = nb1.y;
        Bs[q][lcol + 2][lrow + 64] = nb1.z; Bs[q][lcol + 3][lrow + 64] = nb1.w;
        __syncthreads();
        p = q;
    }

    // last slab
#pragma unroll
    for (int kk = 0; kk < BK; ++kk) {
        float4 a0 = *(const float4*)&As[p][kk][ty * 8];
        float4 a1 = *(const float4*)&As[p][kk][ty * 8 + 4];
        float4 b0 = *(const float4*)&Bs[p][kk][tx * 8];
        float4 b1 = *(const float4*)&Bs[p][kk][tx * 8 + 4];
        float ra[8] = {a0.x, a0.y, a0.z, a0.w, a1.x, a1.y, a1.z, a1.w};
        float rb[8] = {b0.x, b0.y, b0.z, b0.w, b1.x, b1.y, b1.z, b1.w};
#pragma unroll
        for (int i = 0; i < 8; ++i)
#pragma unroll
            for (int j = 0; j < 8; ++j)
                acc[i][j] = fmaf(ra[i], rb[j], acc[i][j]);
    }

#pragma unroll
    for (int i = 0; i < 8; ++i) {
        float4* cp = (float4*)(C + (size_t)(bm + ty * 8 + i) * N + bn + tx * 8);
        cp[0] = make_float4(acc[i][0], acc[i][1], acc[i][2], acc[i][3]);
        cp[1] = make_float4(acc[i][4], acc[i][5], acc[i][6], acc[i][7]);
    }
}

// ============================================================================
// RoPE + rearrange: qkv (B*T, 3C) -> Q/K/V (B*H, T, hd)
// ============================================================================
__global__ __launch_bounds__(256) void rope_rearrange(const float* __restrict__ qkv)
{
    int idx = blockIdx.x * blockDim.x + threadIdx.x;
    if (idx >= B_ * T_ * H_ * (HD_ / 2)) return;

    int i = idx & 31;               // pair index 0..31
    int h = (idx >> 5) & 15;
    int t = (idx >> 9) & 2047;
    int b = idx >> 20;

    const float* src = qkv + (size_t)(b * T_ + t) * QKV_N + h * HD_ + 2 * i;

    double inv = exp2(-(double)i * (13.287712379549449595 / 32.0)); // 10000^(-i/32)
    double ang = (double)t * inv;
    double ds, dc;
    sincos(ang, &ds, &dc);
    float s = (float)ds, c = (float)dc;

    float q0 = src[0],       q1 = src[1];
    float k0 = src[C_],      k1 = src[C_ + 1];
    float2 v2 = *(const float2*)(src + 2 * C_);

    size_t dst = ((size_t)(b * H_ + h) * T_ + t) * HD_ + 2 * i;
    const float qs = 0.125f;  // 1/sqrt(64)
    g_q[dst]     = (q0 * c - q1 * s) * qs;
    g_q[dst + 1] = (q0 * s + q1 * c) * qs;
    g_k[dst]     = k0 * c - k1 * s;
    g_k[dst + 1] = k0 * s + k1 * c;
    *(float2*)(g_v + dst) = v2;
}

// ============================================================================
// Flash attention v2 (alignment-safe): Bq=128, Bk=64, hd=64.
// 256 threads (16x16), 8x4 microtile.
// smem strides all multiples of 4 floats (float4-aligned):
//   Qs [64][128]  d-major
//   Ks [64][64]   d-major
//   Vs [64][68]   k-major (padded +4)
//   Ps [128][68]  r-major (padded +4); PV loop reads P as float4 along k
// ============================================================================
#define QS_STRIDE 128
#define KS_STRIDE 64
#define VS_STRIDE 68
#define PS_STRIDE 68
#define QS_OFF 0
#define KS_OFF (64 * QS_STRIDE)                 // 8192
#define VS_OFF (KS_OFF + 64 * KS_STRIDE)        // 12288
#define PS_OFF (VS_OFF + 64 * VS_STRIDE)        // 16640
#define FLASH_SMEM ((PS_OFF + 128 * PS_STRIDE) * 4)  // 101376 bytes

__global__ __launch_bounds__(256, 2) void flash_attn()
{
    extern __shared__ float smem[];
    float* Qs = smem + QS_OFF;
    float* Ks = smem + KS_OFF;
    float* Vs = smem + VS_OFF;
    float* Ps = smem + PS_OFF;

    const int bh = blockIdx.y;                // 0..63
    const int b  = bh >> 4;
    const int h  = bh & 15;
    const int q0 = blockIdx.x * 128;

    const float* Qb = g_q + (size_t)bh * T_ * HD_;
    const float* Kb = g_k + (size_t)bh * T_ * HD_;
    const float* Vb = g_v + (size_t)bh * T_ * HD_;

    const int tid = threadIdx.x;
    const int tx = tid & 15;
    const int ty = tid >> 4;
    const int r0 = ty * 8;
    const int c0 = tx * 4;

    // Q loader: each thread loads row lrQ, 32 d-values (8 float4), transposed store
    const int lrQ = tid >> 1;
    const int lcQ = (tid & 1) * 32;
#pragma unroll
    for (int pQ = 0; pQ < 8; ++pQ) {
        int d = lcQ + pQ * 4;
        float4 v = *(const float4*)(Qb + (size_t)(q0 + lrQ) * HD_ + d);
        Qs[(d + 0) * QS_STRIDE + lrQ] = v.x;
        Qs[(d + 1) * QS_STRIDE + lrQ] = v.y;
        Qs[(d + 2) * QS_STRIDE + lrQ] = v.z;
        Qs[(d + 3) * QS_STRIDE + lrQ] = v.w;
    }

    // K/V loader: lr = tid>>2 (0..63), lc = (tid&3)*16
    const int lr = tid >> 2;
    const int lc = (tid & 3) * 16;

    float O[8][4];
    float m[8], l[8];
#pragma unroll
    for (int i = 0; i < 8; ++i) {
        m[i] = -3.0e38f; l[i] = 0.0f;
#pragma unroll
        for (int j = 0; j < 4; ++j) O[i][j] = 0.0f;
    }

    for (int kt = 0; kt < T_ / 64; ++kt) {
        const int k0 = kt * 64;
        __syncthreads();   // previous tile's readers done (also covers Qs stores)
#pragma unroll
        for (int pp = 0; pp < 4; ++pp) {
            int d = lc + pp * 4;
            float4 kv = *(const float4*)(Kb + (size_t)(k0 + lr) * HD_ + d);
            Ks[(d + 0) * KS_STRIDE + lr] = kv.x;
            Ks[(d + 1) * KS_STRIDE + lr] = kv.y;
            Ks[(d + 2) * KS_STRIDE + lr] = kv.z;
            Ks[(d + 3) * KS_STRIDE + lr] = kv.w;
            float4 vv = *(const float4*)(Vb + (size_t)(k0 + lr) * HD_ + d);
            *(float4*)(Vs + lr * VS_STRIDE + d) = vv;
        }
        __syncthreads();

        // S = Q K^T (scale folded into Q)
        float acc[8][4];
#pragma unroll
        for (int i = 0; i < 8; ++i)
#pragma unroll
            for (int j = 0; j < 4; ++j) acc[i][j] = 0.0f;

#pragma unroll 4
        for (int d = 0; d < 64; ++d) {
            float4 a0 = *(const float4*)(Qs + d * QS_STRIDE + r0);
            float4 a1 = *(const float4*)(Qs + d * QS_STRIDE + r0 + 4);
            float4 b4 = *(const float4*)(Ks + d * KS_STRIDE + c0);
            float ra[8] = {a0.x, a0.y, a0.z, a0.w, a1.x, a1.y, a1.z, a1.w};
            float rb[4] = {b4.x, b4.y, b4.z, b4.w};
#pragma unroll
            for (int i = 0; i < 8; ++i)
#pragma unroll
                for (int j = 0; j < 4; ++j)
                    acc[i][j] = fmaf(ra[i], rb[j], acc[i][j]);
        }

        // online softmax (rows shared by 16 tx-lanes within half-warp)
#pragma unroll
        for (int i = 0; i < 8; ++i) {
            float mt = fmaxf(fmaxf(acc[i][0], acc[i][1]), fmaxf(acc[i][2], acc[i][3]));
#pragma unroll
            for (int off = 1; off < 16; off <<= 1)
                mt = fmaxf(mt, __shfl_xor_sync(0xffffffffu, mt, off));
            float mn = fmaxf(m[i], mt);
            float corr = __expf(m[i] - mn);
            m[i] = mn;
            l[i] *= corr;
#pragma unroll
            for (int j = 0; j < 4; ++j) O[i][j] *= corr;

            float rs = 0.0f;
#pragma unroll
            for (int j = 0; j < 4; ++j) {
                float pv = __expf(acc[i][j] - mn);
                acc[i][j] = pv;
                rs += pv;
            }
#pragma unroll
            for (int off = 1; off < 16; off <<= 1)
                rs += __shfl_xor_sync(0xffffffffu, rs, off);
            l[i] += rs;
        }

        // store P row-major: Ps[r][k] (aligned, conflict-free float4 stores)
#pragma unroll
        for (int i = 0; i < 8; ++i)
            *(float4*)(Ps + (r0 + i) * PS_STRIDE + c0) =
                make_float4(acc[i][0], acc[i][1], acc[i][2], acc[i][3]);
        __syncthreads();

        // O += P @ V : iterate k in blocks of 4, read P as float4 along k
#pragma unroll 2
        for (int kk4 = 0; kk4 < 16; ++kk4) {
            const int kk = kk4 * 4;
            float4 v0 = *(const float4*)(Vs + (kk + 0) * VS_STRIDE + c0);
            float4 v1 = *(const float4*)(Vs + (kk + 1) * VS_STRIDE + c0);
            float4 v2 = *(const float4*)(Vs + (kk + 2) * VS_STRIDE + c0);
            float4 v3 = *(const float4*)(Vs + (kk + 3) * VS_STRIDE + c0);
#pragma unroll
            for (int i = 0; i < 8; ++i) {
                float4 pv = *(const float4*)(Ps + (r0 + i) * PS_STRIDE + kk);
                O[i][0] = fmaf(pv.x, v0.x, O[i][0]);
                O[i][1] = fmaf(pv.x, v0.y, O[i][1]);
                O[i][2] = fmaf(pv.x, v0.z, O[i][2]);
                O[i][3] = fmaf(pv.x, v0.w, O[i][3]);
                O[i][0] = fmaf(pv.y, v1.x, O[i][0]);
                O[i][1] = fmaf(pv.y, v1.y, O[i][1]);
                O[i][2] = fmaf(pv.y, v1.z, O[i][2]);
                O[i][3] = fmaf(pv.y, v1.w, O[i][3]);
                O[i][0] = fmaf(pv.z, v2.x, O[i][0]);
                O[i][1] = fmaf(pv.z, v2.y, O[i][1]);
                O[i][2] = fmaf(pv.z, v2.z, O[i][2]);
                O[i][3] = fmaf(pv.z, v2.w, O[i][3]);
                O[i][0] = fmaf(pv.w, v3.x, O[i][0]);
                O[i][1] = fmaf(pv.w, v3.y, O[i][1]);
                O[i][2] = fmaf(pv.w, v3.z, O[i][2]);
                O[i][3] = fmaf(pv.w, v3.w, O[i][3]);
            }
        }
    }

    // epilogue: normalize, write to (B, T, C)
#pragma unroll
    for (int i = 0; i < 8; ++i) {
        float rl = 1.0f / l[i];
        float4 o = make_float4(O[i][0] * rl, O[i][1] * rl, O[i][2] * rl, O[i][3] * rl);
        *(float4*)(g_y + (size_t)(b * T_ + q0 + r0 + i) * C_ + h * HD_ + c0) = o;
    }
}

// ============================================================================
// launch
// ============================================================================
extern "C" void kernel_launch(void* const* d_in, const int* in_sizes, int n_in,
                              void* d_out, int out_size)
{
    const float* x      = (const float*)d_in[0];
    const float* w_attn = (const float*)d_in[1];
    const float* w_proj = (const float*)d_in[2];
    float* out = (float*)d_out;

    float* qkv_ptr; cudaGetSymbolAddress((void**)&qkv_ptr, g_qkv);
    float* y_ptr;   cudaGetSymbolAddress((void**)&y_ptr,   g_y);

    cudaFuncSetAttribute(flash_attn, cudaFuncAttributeMaxDynamicSharedMemorySize, FLASH_SMEM);

    // 1) QKV = x @ w_attn^T : (8192, 3072)
    gemm_nt<<<dim3(QKV_N / BN, M_ROWS / BM), 256>>>(x, w_attn, qkv_ptr, M_ROWS, QKV_N, C_);

    // 2) RoPE + rearrange
    {
        int n = B_ * T_ * H_ * (HD_ / 2);
        rope_rearrange<<<(n + 255) / 256, 256>>>(qkv_ptr);
    }

    // 3) flash attention -> g_y (B,T,C)
    flash_attn<<<dim3(T_ / 128, B_ * H_), 256, FLASH_SMEM>>>();

    // 4) out = y @ w_proj^T : (8192, 1024)
    gemm_nt<<<dim3(C_ / BN, M_ROWS / BM), 256>>>(y_ptr, w_proj, out, M_ROWS, C_, C_);
}